// round 3
// baseline (speedup 1.0000x reference)
#include <cuda_runtime.h>
#include <stdint.h>

#define NB 32768   // batch rows
#define NK 1024    // codebook entries
#define ND 512     // feature dim
#define EPSN 1e-8f

// ---------------- device scratch (no allocs allowed) ----------------
__device__ float g_sim[(size_t)NB * NK];   // 128 MB similarity scratch
__device__ float g_xinv[NB];
__device__ float g_cinv[NK];

// ---------------- threefry2x32 (JAX-exact, 20 rounds) ----------------
__device__ __forceinline__ uint2 tf2x32_dev(uint32_t k0, uint32_t k1,
                                            uint32_t x0, uint32_t x1) {
    uint32_t k2 = k0 ^ k1 ^ 0x1BD11BDAu;
    x0 += k0; x1 += k1;
#define TF_ROT(r) { x0 += x1; x1 = __funnelshift_l(x1, x1, r); x1 ^= x0; }
    TF_ROT(13) TF_ROT(15) TF_ROT(26) TF_ROT(6)
    x0 += k1; x1 += k2 + 1u;
    TF_ROT(17) TF_ROT(29) TF_ROT(16) TF_ROT(24)
    x0 += k2; x1 += k0 + 2u;
    TF_ROT(13) TF_ROT(15) TF_ROT(26) TF_ROT(6)
    x0 += k0; x1 += k1 + 3u;
    TF_ROT(17) TF_ROT(29) TF_ROT(16) TF_ROT(24)
    x0 += k1; x1 += k2 + 4u;
    TF_ROT(13) TF_ROT(15) TF_ROT(26) TF_ROT(6)
    x0 += k2; x1 += k0 + 5u;
#undef TF_ROT
    return make_uint2(x0, x1);
}

// partitionable random_bits(32): XOR-fold both output words
__device__ __forceinline__ uint32_t rbits32(uint32_t k0, uint32_t k1, uint32_t flat) {
    uint2 r = tf2x32_dev(k0, k1, 0u, flat);   // counter = (hi=0, lo=flat)
    return r.x ^ r.y;
}

// uniform(1e-20, 1.0) -> gumbel, matching JAX bit-exactly on the uniform
__device__ __forceinline__ float gumbel_bits(uint32_t bits) {
    float f = __uint_as_float((bits >> 9) | 0x3f800000u) - 1.0f; // [0,1)
    float u = fmaxf(f + 1e-20f, 1e-20f);
    return -logf(-logf(u));
}

// ---------------- inverse norms ----------------
__global__ void inv_norm_kernel(const float* __restrict__ src, int which) {
    const int row = blockIdx.x;
    const float4* p = (const float4*)(src + (size_t)row * ND);
    float4 v = p[threadIdx.x];                    // 128 threads * 4 = 512
    float s = v.x * v.x + v.y * v.y + v.z * v.z + v.w * v.w;
#pragma unroll
    for (int o = 16; o; o >>= 1) s += __shfl_xor_sync(0xffffffffu, s, o);
    __shared__ float sm[4];
    if ((threadIdx.x & 31) == 0) sm[threadIdx.x >> 5] = s;
    __syncthreads();
    if (threadIdx.x == 0) {
        float tot = sm[0] + sm[1] + sm[2] + sm[3];
        float inv = 1.0f / fmaxf(sqrtf(tot), EPSN);
        if (which == 0) g_xinv[row] = inv; else g_cinv[row] = inv;
    }
}

// ---------------- fp32 SIMT GEMM:  sim = (X @ C^T) * xinv * cinv ----------------
__global__ __launch_bounds__(256, 2) void gemm_kernel(const float* __restrict__ A,
                                                      const float* __restrict__ Bm) {
    __shared__ float As[16][128];
    __shared__ float Bs[16][128];
    const int bm = blockIdx.y * 128;
    const int bn = blockIdx.x * 128;
    const int tid = threadIdx.x;
    const int ty = tid >> 4;   // 0..15 -> 8 rows each
    const int tx = tid & 15;   // 0..15 -> 8 cols each

    float acc[8][8];
#pragma unroll
    for (int i = 0; i < 8; i++)
#pragma unroll
        for (int j = 0; j < 8; j++) acc[i][j] = 0.0f;

    for (int kt = 0; kt < ND; kt += 16) {
#pragma unroll
        for (int l = 0; l < 2; l++) {
            int f4 = tid + l * 256;          // 512 float4 per tile
            int r  = f4 >> 2;
            int c4 = (f4 & 3) << 2;
            float4 va = *(const float4*)(A  + (size_t)(bm + r) * ND + kt + c4);
            As[c4 + 0][r] = va.x; As[c4 + 1][r] = va.y;
            As[c4 + 2][r] = va.z; As[c4 + 3][r] = va.w;
            float4 vb = *(const float4*)(Bm + (size_t)(bn + r) * ND + kt + c4);
            Bs[c4 + 0][r] = vb.x; Bs[c4 + 1][r] = vb.y;
            Bs[c4 + 2][r] = vb.z; Bs[c4 + 3][r] = vb.w;
        }
        __syncthreads();
#pragma unroll
        for (int kk = 0; kk < 16; kk++) {
            float af[8], bf[8];
            *(float4*)(af)     = *(const float4*)&As[kk][ty * 8];
            *(float4*)(af + 4) = *(const float4*)&As[kk][ty * 8 + 4];
            *(float4*)(bf)     = *(const float4*)&Bs[kk][tx * 8];
            *(float4*)(bf + 4) = *(const float4*)&Bs[kk][tx * 8 + 4];
#pragma unroll
            for (int i = 0; i < 8; i++)
#pragma unroll
                for (int j = 0; j < 8; j++)
                    acc[i][j] = fmaf(af[i], bf[j], acc[i][j]);
        }
        __syncthreads();
    }

    float xi[8], cj[8];
#pragma unroll
    for (int i = 0; i < 8; i++) xi[i] = g_xinv[bm + ty * 8 + i];
#pragma unroll
    for (int j = 0; j < 8; j++) cj[j] = g_cinv[bn + tx * 8 + j];
#pragma unroll
    for (int i = 0; i < 8; i++) {
        float* dst = g_sim + (size_t)(bm + ty * 8 + i) * NK + bn + tx * 8;
#pragma unroll
        for (int j4 = 0; j4 < 2; j4++) {
            float4 o;
            o.x = acc[i][j4 * 4 + 0] * xi[i] * cj[j4 * 4 + 0];
            o.y = acc[i][j4 * 4 + 1] * xi[i] * cj[j4 * 4 + 1];
            o.z = acc[i][j4 * 4 + 2] * xi[i] * cj[j4 * 4 + 2];
            o.w = acc[i][j4 * 4 + 3] * xi[i] * cj[j4 * 4 + 3];
            *(float4*)(dst + j4 * 4) = o;
        }
    }
}

// ---------------- per-row: gumbel noise, argmax, softmax, gather ----------------
__global__ __launch_bounds__(256) void rowops_kernel(
    const float* __restrict__ cb,
    float* __restrict__ zq, float* __restrict__ wout, float* __restrict__ idxout,
    uint32_t kh0, uint32_t kh1, uint32_t ks0, uint32_t ks1) {

    const int b = blockIdx.x;
    const int t = threadIdx.x;
    const int k0 = t << 2;
    const unsigned FULL = 0xffffffffu;
    const int lane = t & 31, warp = t >> 5;

    float4 s4 = *(const float4*)(g_sim + (size_t)b * NK + k0);
    float sim[4] = {s4.x, s4.y, s4.z, s4.w};
    float vs[4];
    float bv = -1e30f; int bk = 0;
#pragma unroll
    for (int j = 0; j < 4; j++) {
        uint32_t flat = (uint32_t)b * (uint32_t)NK + (uint32_t)(k0 + j);
        float vh = sim[j] + gumbel_bits(rbits32(kh0, kh1, flat));
        vs[j]    = sim[j] + gumbel_bits(rbits32(ks0, ks1, flat));
        if (vh > bv) { bv = vh; bk = k0 + j; }
    }

    __shared__ float sred[8];
    __shared__ int   sredi[8];
    __shared__ int   s_idx;
    __shared__ float s_max, s_sum;

    // --- block argmax (first-occurrence tie-break) ---
#pragma unroll
    for (int o = 16; o; o >>= 1) {
        float ov = __shfl_down_sync(FULL, bv, o);
        int   ok = __shfl_down_sync(FULL, bk, o);
        if (ov > bv || (ov == bv && ok < bk)) { bv = ov; bk = ok; }
    }
    if (lane == 0) { sred[warp] = bv; sredi[warp] = bk; }
    __syncthreads();
    if (t == 0) {
        float v = sred[0]; int k = sredi[0];
#pragma unroll
        for (int w = 1; w < 8; w++)
            if (sred[w] > v || (sred[w] == v && sredi[w] < k)) { v = sred[w]; k = sredi[w]; }
        s_idx = k;
    }
    __syncthreads();

    // --- softmax max ---
    float m = fmaxf(fmaxf(vs[0], vs[1]), fmaxf(vs[2], vs[3]));
#pragma unroll
    for (int o = 16; o; o >>= 1) m = fmaxf(m, __shfl_xor_sync(FULL, m, o));
    if (lane == 0) sred[warp] = m;
    __syncthreads();
    if (t == 0) {
        float mm = sred[0];
#pragma unroll
        for (int w = 1; w < 8; w++) mm = fmaxf(mm, sred[w]);
        s_max = mm;
    }
    __syncthreads();
    m = s_max;

    // --- softmax sum ---
    float p[4]; float ls = 0.0f;
#pragma unroll
    for (int j = 0; j < 4; j++) { p[j] = expf(vs[j] - m); ls += p[j]; }
#pragma unroll
    for (int o = 16; o; o >>= 1) ls += __shfl_xor_sync(FULL, ls, o);
    if (lane == 0) sred[warp] = ls;
    __syncthreads();
    if (t == 0) {
        float ss = 0.0f;
#pragma unroll
        for (int w = 0; w < 8; w++) ss += sred[w];
        s_sum = ss;
    }
    __syncthreads();

    float inv = 1.0f / s_sum;
    float4 o4 = make_float4(p[0] * inv, p[1] * inv, p[2] * inv, p[3] * inv);
    *(float4*)(wout + (size_t)b * NK + k0) = o4;

    // --- z_q gather (codebook row, raw) + index ---
    int idx = s_idx;
    const float2* crow = (const float2*)(cb + (size_t)idx * ND);
    ((float2*)(zq + (size_t)b * ND))[t] = crow[t];   // 256 * float2 = 512
    if (t == 0) idxout[b] = (float)idx;
}

// ---------------- host-side threefry for key derivation ----------------
static void tf2x32_host(uint32_t k0, uint32_t k1, uint32_t x0, uint32_t x1,
                        uint32_t* o0, uint32_t* o1) {
    uint32_t k2 = k0 ^ k1 ^ 0x1BD11BDAu;
    x0 += k0; x1 += k1;
#define TF_ROT(r) { x0 += x1; x1 = (x1 << (r)) | (x1 >> (32 - (r))); x1 ^= x0; }
    TF_ROT(13) TF_ROT(15) TF_ROT(26) TF_ROT(6)
    x0 += k1; x1 += k2 + 1u;
    TF_ROT(17) TF_ROT(29) TF_ROT(16) TF_ROT(24)
    x0 += k2; x1 += k0 + 2u;
    TF_ROT(13) TF_ROT(15) TF_ROT(26) TF_ROT(6)
    x0 += k0; x1 += k1 + 3u;
    TF_ROT(17) TF_ROT(29) TF_ROT(16) TF_ROT(24)
    x0 += k1; x1 += k2 + 4u;
    TF_ROT(13) TF_ROT(15) TF_ROT(26) TF_ROT(6)
    x0 += k2; x1 += k0 + 5u;
#undef TF_ROT
    *o0 = x0; *o1 = x1;
}

extern "C" void kernel_launch(void* const* d_in, const int* in_sizes, int n_in,
                              void* d_out, int out_size) {
    const float* state = (const float*)d_in[0];   // (32768, 512)
    const float* cb    = (const float*)d_in[1];   // (1024, 512)

    float* out  = (float*)d_out;
    float* zq   = out;                                      // 32768*512
    float* w    = out + (size_t)NB * ND;                    // 32768*1024
    float* idxp = out + (size_t)NB * ND + (size_t)NB * NK;  // 32768

    // jax.random.key(42) == (0, 42); partitionable fold-like split:
    // key_i = (word0, word1) of threefry(key, (0, i));  kh = i0, ks = i1
    uint32_t kh0, kh1, ks0, ks1;
    tf2x32_host(0u, 42u, 0u, 0u, &kh0, &kh1);
    tf2x32_host(0u, 42u, 0u, 1u, &ks0, &ks1);

    inv_norm_kernel<<<NB, 128>>>(state, 0);
    inv_norm_kernel<<<NK, 128>>>(cb, 1);

    dim3 ggrid(NK / 128, NB / 128);
    gemm_kernel<<<ggrid, 256>>>(state, cb);

    rowops_kernel<<<NB, 256>>>(cb, zq, w, idxp, kh0, kh1, ks0, ks1);
}

// round 4
// speedup vs baseline: 1.0431x; 1.0431x over previous
#include <cuda_runtime.h>
#include <stdint.h>

#define NB 32768   // batch rows
#define NK 1024    // codebook entries
#define ND 512     // feature dim
#define EPSN 1e-8f

// ---------------- device scratch (no allocs allowed) ----------------
__device__ float g_sim[(size_t)NB * NK];   // 128 MB similarity scratch
__device__ float g_xinv[NB];
__device__ float g_cinv[NK];

// ---------------- packed f32x2 helpers (Blackwell) ----------------
#define FMA_F32X2(d, a, b, c) \
    asm("fma.rn.f32x2 %0, %1, %2, %3;" : "=l"(d) : "l"(a), "l"(b), "l"(c))
#define PACK_DUP_F32X2(out, v) \
    asm("mov.b64 %0, {%1, %1};" : "=l"(out) : "r"(v))
#define UNPACK_F32X2(lo, hi, in) \
    asm("mov.b64 {%0, %1}, %2;" : "=r"(lo), "=r"(hi) : "l"(in))

// ---------------- threefry2x32 (JAX-exact, 20 rounds) ----------------
__device__ __forceinline__ uint2 tf2x32_dev(uint32_t k0, uint32_t k1,
                                            uint32_t x0, uint32_t x1) {
    uint32_t k2 = k0 ^ k1 ^ 0x1BD11BDAu;
    x0 += k0; x1 += k1;
#define TF_ROT(r) { x0 += x1; x1 = __funnelshift_l(x1, x1, r); x1 ^= x0; }
    TF_ROT(13) TF_ROT(15) TF_ROT(26) TF_ROT(6)
    x0 += k1; x1 += k2 + 1u;
    TF_ROT(17) TF_ROT(29) TF_ROT(16) TF_ROT(24)
    x0 += k2; x1 += k0 + 2u;
    TF_ROT(13) TF_ROT(15) TF_ROT(26) TF_ROT(6)
    x0 += k0; x1 += k1 + 3u;
    TF_ROT(17) TF_ROT(29) TF_ROT(16) TF_ROT(24)
    x0 += k1; x1 += k2 + 4u;
    TF_ROT(13) TF_ROT(15) TF_ROT(26) TF_ROT(6)
    x0 += k2; x1 += k0 + 5u;
#undef TF_ROT
    return make_uint2(x0, x1);
}

// partitionable random_bits(32): XOR-fold both output words
__device__ __forceinline__ uint32_t rbits32(uint32_t k0, uint32_t k1, uint32_t flat) {
    uint2 r = tf2x32_dev(k0, k1, 0u, flat);   // counter = (hi=0, lo=flat)
    return r.x ^ r.y;
}

// JAX uniform(1e-20, 1.0) from raw bits (bit-identical to passing round)
__device__ __forceinline__ float uniform_bits(uint32_t bits) {
    float f = __uint_as_float((bits >> 9) | 0x3f800000u) - 1.0f; // [0,1)
    return fmaxf(f + 1e-20f, 1e-20f);
}

// ---------------- inverse norms ----------------
__global__ void inv_norm_kernel(const float* __restrict__ src, int which) {
    const int row = blockIdx.x;
    const float4* p = (const float4*)(src + (size_t)row * ND);
    float4 v = p[threadIdx.x];                    // 128 threads * 4 = 512
    float s = v.x * v.x + v.y * v.y + v.z * v.z + v.w * v.w;
#pragma unroll
    for (int o = 16; o; o >>= 1) s += __shfl_xor_sync(0xffffffffu, s, o);
    __shared__ float sm[4];
    if ((threadIdx.x & 31) == 0) sm[threadIdx.x >> 5] = s;
    __syncthreads();
    if (threadIdx.x == 0) {
        float tot = sm[0] + sm[1] + sm[2] + sm[3];
        float inv = 1.0f / fmaxf(sqrtf(tot), EPSN);
        if (which == 0) g_xinv[row] = inv; else g_cinv[row] = inv;
    }
}

// ---------------- f32x2 SIMT GEMM:  sim = (X @ C^T) * xinv * cinv ----------------
__global__ __launch_bounds__(256, 2) void gemm_kernel(const float* __restrict__ A,
                                                      const float* __restrict__ Bm) {
    __shared__ float As[16][128];
    __shared__ float Bs[16][128];
    const int bm = blockIdx.y * 128;
    const int bn = blockIdx.x * 128;
    const int tid = threadIdx.x;
    const int ty = tid >> 4;   // 0..15 -> 8 rows each
    const int tx = tid & 15;   // 0..15 -> 8 cols each

    // packed accumulators: acc2[i][j2] = (col 2*j2, col 2*j2+1) for row i
    uint64_t acc2[8][4];
#pragma unroll
    for (int i = 0; i < 8; i++)
#pragma unroll
        for (int j = 0; j < 4; j++) acc2[i][j] = 0ull;

    for (int kt = 0; kt < ND; kt += 16) {
#pragma unroll
        for (int l = 0; l < 2; l++) {
            int f4 = tid + l * 256;          // 512 float4 per tile
            int r  = f4 >> 2;
            int c4 = (f4 & 3) << 2;
            float4 va = *(const float4*)(A  + (size_t)(bm + r) * ND + kt + c4);
            As[c4 + 0][r] = va.x; As[c4 + 1][r] = va.y;
            As[c4 + 2][r] = va.z; As[c4 + 3][r] = va.w;
            float4 vb = *(const float4*)(Bm + (size_t)(bn + r) * ND + kt + c4);
            Bs[c4 + 0][r] = vb.x; Bs[c4 + 1][r] = vb.y;
            Bs[c4 + 2][r] = vb.z; Bs[c4 + 3][r] = vb.w;
        }
        __syncthreads();
#pragma unroll
        for (int kk = 0; kk < 16; kk++) {
            float af[8];
            *(float4*)(af)     = *(const float4*)&As[kk][ty * 8];
            *(float4*)(af + 4) = *(const float4*)&As[kk][ty * 8 + 4];
            // B pairs come packed for free from 128-bit shared loads
            ulonglong2 b01 = *(const ulonglong2*)&Bs[kk][tx * 8];
            ulonglong2 b23 = *(const ulonglong2*)&Bs[kk][tx * 8 + 4];
            uint64_t b2[4] = {b01.x, b01.y, b23.x, b23.y};
#pragma unroll
            for (int i = 0; i < 8; i++) {
                uint64_t a2;
                PACK_DUP_F32X2(a2, __float_as_uint(af[i]));
#pragma unroll
                for (int j = 0; j < 4; j++)
                    FMA_F32X2(acc2[i][j], a2, b2[j], acc2[i][j]);
            }
        }
        __syncthreads();
    }

    float xi[8], cj[8];
#pragma unroll
    for (int i = 0; i < 8; i++) xi[i] = g_xinv[bm + ty * 8 + i];
#pragma unroll
    for (int j = 0; j < 8; j++) cj[j] = g_cinv[bn + tx * 8 + j];
#pragma unroll
    for (int i = 0; i < 8; i++) {
        float* dst = g_sim + (size_t)(bm + ty * 8 + i) * NK + bn + tx * 8;
#pragma unroll
        for (int j4 = 0; j4 < 2; j4++) {
            uint32_t u0, u1, u2, u3;
            UNPACK_F32X2(u0, u1, acc2[i][j4 * 2 + 0]);
            UNPACK_F32X2(u2, u3, acc2[i][j4 * 2 + 1]);
            float4 o;
            o.x = __uint_as_float(u0) * xi[i] * cj[j4 * 4 + 0];
            o.y = __uint_as_float(u1) * xi[i] * cj[j4 * 4 + 1];
            o.z = __uint_as_float(u2) * xi[i] * cj[j4 * 4 + 2];
            o.w = __uint_as_float(u3) * xi[i] * cj[j4 * 4 + 3];
            *(float4*)(dst + j4 * 4) = o;
        }
    }
}

// ---------------- per-row: gumbel noise, argmax, softmax, gather ----------------
// Algebraic form: with e = -log(u) (exponential variate),
//   softmax(sim + g)_j  with g = -log(e)  ==>  (exp(sim_j)/e_j) / sum
//   argmax(sim + g)     ==  argmax exp(sim)/e_hard   (monotone transform)
__global__ __launch_bounds__(256) void rowops_kernel(
    const float* __restrict__ cb,
    float* __restrict__ zq, float* __restrict__ wout, float* __restrict__ idxout,
    uint32_t kh0, uint32_t kh1, uint32_t ks0, uint32_t ks1) {

    const int b = blockIdx.x;
    const int t = threadIdx.x;
    const int k0 = t << 2;
    const unsigned FULL = 0xffffffffu;
    const int lane = t & 31, warp = t >> 5;

    float4 s4 = *(const float4*)(g_sim + (size_t)b * NK + k0);
    float sim[4] = {s4.x, s4.y, s4.z, s4.w};
    float ts[4];
    float bv = -1.0f; int bk = 0;
#pragma unroll
    for (int j = 0; j < 4; j++) {
        uint32_t flat = (uint32_t)b * (uint32_t)NK + (uint32_t)(k0 + j);
        float uh = uniform_bits(rbits32(kh0, kh1, flat));
        float us = uniform_bits(rbits32(ks0, ks1, flat));
        float eh = -logf(uh);          // precise: feeds argmax
        float es = -__logf(us);        // fast: feeds weights only (1e-3 tol)
        float texp = expf(sim[j]);     // shared between hard & soft
        float h = texp / eh;           // precise div: argmax score
        ts[j] = __fdividef(texp, es);  // softmax numerator
        if (h > bv) { bv = h; bk = k0 + j; }
    }

    __shared__ float sred[8];
    __shared__ int   sredi[8];
    __shared__ int   s_idx;
    __shared__ float s_sum;

    // --- block argmax (first-occurrence tie-break) ---
#pragma unroll
    for (int o = 16; o; o >>= 1) {
        float ov = __shfl_down_sync(FULL, bv, o);
        int   ok = __shfl_down_sync(FULL, bk, o);
        if (ov > bv || (ov == bv && ok < bk)) { bv = ov; bk = ok; }
    }
    if (lane == 0) { sred[warp] = bv; sredi[warp] = bk; }
    __syncthreads();
    if (t == 0) {
        float v = sred[0]; int k = sredi[0];
#pragma unroll
        for (int w = 1; w < 8; w++)
            if (sred[w] > v || (sred[w] == v && sredi[w] < k)) { v = sred[w]; k = sredi[w]; }
        s_idx = k;
    }

    // --- softmax sum (no max pass needed: ts bounded by ~5e7) ---
    float ls = (ts[0] + ts[1]) + (ts[2] + ts[3]);
#pragma unroll
    for (int o = 16; o; o >>= 1) ls += __shfl_xor_sync(FULL, ls, o);
    __syncthreads();   // protect sred reuse
    if (lane == 0) sred[warp] = ls;
    __syncthreads();
    if (t == 0) {
        float ss = 0.0f;
#pragma unroll
        for (int w = 0; w < 8; w++) ss += sred[w];
        s_sum = ss;
    }
    __syncthreads();

    float inv = 1.0f / s_sum;
    float4 o4 = make_float4(ts[0] * inv, ts[1] * inv, ts[2] * inv, ts[3] * inv);
    *(float4*)(wout + (size_t)b * NK + k0) = o4;

    // --- z_q gather (codebook row, raw) + index ---
    int idx = s_idx;
    const float2* crow = (const float2*)(cb + (size_t)idx * ND);
    ((float2*)(zq + (size_t)b * ND))[t] = crow[t];   // 256 * float2 = 512
    if (t == 0) idxout[b] = (float)idx;
}

// ---------------- host-side threefry for key derivation ----------------
static void tf2x32_host(uint32_t k0, uint32_t k1, uint32_t x0, uint32_t x1,
                        uint32_t* o0, uint32_t* o1) {
    uint32_t k2 = k0 ^ k1 ^ 0x1BD11BDAu;
    x0 += k0; x1 += k1;
#define TF_ROT(r) { x0 += x1; x1 = (x1 << (r)) | (x1 >> (32 - (r))); x1 ^= x0; }
    TF_ROT(13) TF_ROT(15) TF_ROT(26) TF_ROT(6)
    x0 += k1; x1 += k2 + 1u;
    TF_ROT(17) TF_ROT(29) TF_ROT(16) TF_ROT(24)
    x0 += k2; x1 += k0 + 2u;
    TF_ROT(13) TF_ROT(15) TF_ROT(26) TF_ROT(6)
    x0 += k0; x1 += k1 + 3u;
    TF_ROT(17) TF_ROT(29) TF_ROT(16) TF_ROT(24)
    x0 += k1; x1 += k2 + 4u;
    TF_ROT(13) TF_ROT(15) TF_ROT(26) TF_ROT(6)
    x0 += k2; x1 += k0 + 5u;
#undef TF_ROT
    *o0 = x0; *o1 = x1;
}

extern "C" void kernel_launch(void* const* d_in, const int* in_sizes, int n_in,
                              void* d_out, int out_size) {
    const float* state = (const float*)d_in[0];   // (32768, 512)
    const float* cb    = (const float*)d_in[1];   // (1024, 512)

    float* out  = (float*)d_out;
    float* zq   = out;                                      // 32768*512
    float* w    = out + (size_t)NB * ND;                    // 32768*1024
    float* idxp = out + (size_t)NB * ND + (size_t)NB * NK;  // 32768

    // jax.random.key(42) == (0, 42); partitionable fold-like split:
    // key_i = (word0, word1) of threefry(key, (0, i));  kh = i0, ks = i1
    uint32_t kh0, kh1, ks0, ks1;
    tf2x32_host(0u, 42u, 0u, 0u, &kh0, &kh1);
    tf2x32_host(0u, 42u, 0u, 1u, &ks0, &ks1);

    inv_norm_kernel<<<NB, 128>>>(state, 0);
    inv_norm_kernel<<<NK, 128>>>(cb, 1);

    dim3 ggrid(NK / 128, NB / 128);
    gemm_kernel<<<ggrid, 256>>>(state, cb);

    rowops_kernel<<<NB, 256>>>(cb, zq, w, idxp, kh0, kh1, ks0, ks1);
}

// round 7
// speedup vs baseline: 1.7829x; 1.7091x over previous
#include <cuda_runtime.h>
#include <cuda_bf16.h>
#include <stdint.h>

#define NB 32768   // batch rows
#define NK 1024    // codebook entries
#define ND 512     // feature dim
#define KBIG 1536  // 3-term split K: A=[hi|lo|hi], B=[hi|hi|lo]
#define EPSN 1e-8f

// ---------------- device scratch (no allocs allowed) ----------------
__device__ float g_sim[(size_t)NB * NK];   // 128 MB similarity scratch
__device__ float g_xinv[NB];
__device__ float g_cinv[NK];
__device__ __nv_bfloat16 g_ab[(size_t)NB * KBIG];  // 96 MB  [Ahi | Alo | Ahi]
__device__ __nv_bfloat16 g_bb[(size_t)NK * KBIG];  //  3 MB  [Bhi | Bhi | Blo]

// ---------------- PTX helpers (baseline ISA only: sm_80+) ----------------
__device__ __forceinline__ uint32_t smem_u32(const void* p) {
    uint32_t a;
    asm("{ .reg .u64 t; cvta.to.shared.u64 t, %1; cvt.u32.u64 %0, t; }" : "=r"(a) : "l"(p));
    return a;
}
#define CP_ASYNC16(saddr, gptr) \
    asm volatile("cp.async.cg.shared.global [%0], [%1], 16;" :: "r"(saddr), "l"(gptr) : "memory")
#define CP_COMMIT() asm volatile("cp.async.commit_group;" ::: "memory")
#define LDSM_X4(r0, r1, r2, r3, addr) \
    asm volatile("ldmatrix.sync.aligned.m8n8.x4.shared.b16 {%0,%1,%2,%3}, [%4];" \
        : "=r"(r0), "=r"(r1), "=r"(r2), "=r"(r3) : "r"(addr))
#define MMA16816(D, A, B) \
    asm volatile("mma.sync.aligned.m16n8k16.row.col.f32.bf16.bf16.f32 " \
        "{%0,%1,%2,%3}, {%4,%5,%6,%7}, {%8,%9}, {%0,%1,%2,%3};" \
        : "+f"((D)[0]), "+f"((D)[1]), "+f"((D)[2]), "+f"((D)[3]) \
        : "r"((A)[0]), "r"((A)[1]), "r"((A)[2]), "r"((A)[3]), "r"((B)[0]), "r"((B)[1]))

// ---------------- threefry2x32 (JAX-exact, 20 rounds) ----------------
__device__ __forceinline__ uint2 tf2x32_dev(uint32_t k0, uint32_t k1,
                                            uint32_t x0, uint32_t x1) {
    uint32_t k2 = k0 ^ k1 ^ 0x1BD11BDAu;
    x0 += k0; x1 += k1;
#define TF_ROT(r) { x0 += x1; x1 = __funnelshift_l(x1, x1, r); x1 ^= x0; }
    TF_ROT(13) TF_ROT(15) TF_ROT(26) TF_ROT(6)
    x0 += k1; x1 += k2 + 1u;
    TF_ROT(17) TF_ROT(29) TF_ROT(16) TF_ROT(24)
    x0 += k2; x1 += k0 + 2u;
    TF_ROT(13) TF_ROT(15) TF_ROT(26) TF_ROT(6)
    x0 += k0; x1 += k1 + 3u;
    TF_ROT(17) TF_ROT(29) TF_ROT(16) TF_ROT(24)
    x0 += k1; x1 += k2 + 4u;
    TF_ROT(13) TF_ROT(15) TF_ROT(26) TF_ROT(6)
    x0 += k2; x1 += k0 + 5u;
#undef TF_ROT
    return make_uint2(x0, x1);
}
__device__ __forceinline__ uint32_t rbits32(uint32_t k0, uint32_t k1, uint32_t flat) {
    uint2 r = tf2x32_dev(k0, k1, 0u, flat);
    return r.x ^ r.y;
}
__device__ __forceinline__ float uniform_bits(uint32_t bits) {
    float f = __uint_as_float((bits >> 9) | 0x3f800000u) - 1.0f;
    return fmaxf(f + 1e-20f, 1e-20f);
}

// ---------------- inverse norms ----------------
__global__ void inv_norm_kernel(const float* __restrict__ src, int which) {
    const int row = blockIdx.x;
    const float4* p = (const float4*)(src + (size_t)row * ND);
    float4 v = p[threadIdx.x];
    float s = v.x * v.x + v.y * v.y + v.z * v.z + v.w * v.w;
#pragma unroll
    for (int o = 16; o; o >>= 1) s += __shfl_xor_sync(0xffffffffu, s, o);
    __shared__ float sm[4];
    if ((threadIdx.x & 31) == 0) sm[threadIdx.x >> 5] = s;
    __syncthreads();
    if (threadIdx.x == 0) {
        float tot = sm[0] + sm[1] + sm[2] + sm[3];
        float inv = 1.0f / fmaxf(sqrtf(tot), EPSN);
        if (which == 0) g_xinv[row] = inv; else g_cinv[row] = inv;
    }
}

// ---------------- fp32 -> 3-term bf16 split ----------------
// A (which=0): [hi | lo | hi];  B (which=1): [hi | hi | lo]
__global__ void split_kernel(const float* __restrict__ src, int which, int n4) {
    int i = blockIdx.x * blockDim.x + threadIdx.x;
    if (i >= n4) return;
    __nv_bfloat16* dst = which ? g_bb : g_ab;
    float4 v = ((const float4*)src)[i];
    int row = i >> 7;             // 128 float4 per 512-float row
    int col = (i & 127) << 2;
    __nv_bfloat16 h0 = __float2bfloat16_rn(v.x), h1 = __float2bfloat16_rn(v.y);
    __nv_bfloat16 h2 = __float2bfloat16_rn(v.z), h3 = __float2bfloat16_rn(v.w);
    __nv_bfloat16 l0 = __float2bfloat16_rn(v.x - __bfloat162float(h0));
    __nv_bfloat16 l1 = __float2bfloat16_rn(v.y - __bfloat162float(h1));
    __nv_bfloat16 l2 = __float2bfloat16_rn(v.z - __bfloat162float(h2));
    __nv_bfloat16 l3 = __float2bfloat16_rn(v.w - __bfloat162float(h3));
    __nv_bfloat162 hA(h0, h1), hB(h2, h3), lA(l0, l1), lB(l2, l3);
    __nv_bfloat16* base = dst + (size_t)row * KBIG + col;
    __nv_bfloat162* s0 = (__nv_bfloat162*)(base);            // slot 0: hi
    __nv_bfloat162* s1 = (__nv_bfloat162*)(base + ND);       // slot 1
    __nv_bfloat162* s2 = (__nv_bfloat162*)(base + 2 * ND);   // slot 2
    s0[0] = hA; s0[1] = hB;
    if (which == 0) {  // A: [hi | lo | hi]
        s1[0] = lA; s1[1] = lB;
        s2[0] = hA; s2[1] = hB;
    } else {           // B: [hi | hi | lo]
        s1[0] = hA; s1[1] = hB;
        s2[0] = lA; s2[1] = lB;
    }
}

// ---------------- bf16 mma.sync GEMM: sim = (Ab @ Bb^T) * xinv * cinv ----------------
#define BM 128
#define BN 128
#define BK 32
#define SSTR 40   // smem row stride in bf16 (32 + 8 pad) -> conflict-free ldmatrix

__global__ __launch_bounds__(256, 2) void gemm_mma_kernel() {
    __shared__ __align__(16) __nv_bfloat16 Asm[2][BM * SSTR];
    __shared__ __align__(16) __nv_bfloat16 Bsm[2][BN * SSTR];

    const int tid = threadIdx.x;
    const int wid = tid >> 5, l = tid & 31;
    const int wm = wid >> 2, wn = wid & 3;           // warp grid 2(m) x 4(n)
    const int bm = blockIdx.y * BM, bn = blockIdx.x * BN;

    uint32_t sA[2] = { smem_u32(Asm[0]), smem_u32(Asm[1]) };
    uint32_t sB[2] = { smem_u32(Bsm[0]), smem_u32(Bsm[1]) };

    float d[4][4][4];
#pragma unroll
    for (int mi = 0; mi < 4; mi++)
#pragma unroll
        for (int ni = 0; ni < 4; ni++)
#pragma unroll
            for (int r = 0; r < 4; r++) d[mi][ni][r] = 0.0f;

#define LOAD_TILE(kt, buf) do { \
    int _k0 = (kt) * BK; \
    { int r = tid >> 2, c = tid & 3; \
      CP_ASYNC16(sA[buf] + r * (SSTR * 2) + c * 16, \
                 g_ab + (size_t)(bm + r) * KBIG + _k0 + c * 8); } \
    { int r = (tid + 256) >> 2, c = tid & 3; \
      CP_ASYNC16(sA[buf] + r * (SSTR * 2) + c * 16, \
                 g_ab + (size_t)(bm + r) * KBIG + _k0 + c * 8); } \
    { int r = tid >> 2, c = tid & 3; \
      CP_ASYNC16(sB[buf] + r * (SSTR * 2) + c * 16, \
                 g_bb + (size_t)(bn + r) * KBIG + _k0 + c * 8); } \
    { int r = (tid + 256) >> 2, c = tid & 3; \
      CP_ASYNC16(sB[buf] + r * (SSTR * 2) + c * 16, \
                 g_bb + (size_t)(bn + r) * KBIG + _k0 + c * 8); } \
    CP_COMMIT(); \
} while (0)

    LOAD_TILE(0, 0);

    for (int kt = 0; kt < KBIG / BK; kt++) {
        if (kt + 1 < KBIG / BK) {
            LOAD_TILE(kt + 1, (kt + 1) & 1);
            asm volatile("cp.async.wait_group 1;" ::: "memory");
        } else {
            asm volatile("cp.async.wait_group 0;" ::: "memory");
        }
        __syncthreads();
        const int buf = kt & 1;

#pragma unroll
        for (int ks = 0; ks < 2; ks++) {
            uint32_t a[4][4];
#pragma unroll
            for (int mi = 0; mi < 4; mi++) {
                int row = wm * 64 + mi * 16 + (l & 15);
                int col = ks * 16 + (l >> 4) * 8;
                LDSM_X4(a[mi][0], a[mi][1], a[mi][2], a[mi][3],
                        sA[buf] + row * (SSTR * 2) + col * 2);
            }
            uint32_t b[4][2];
#pragma unroll
            for (int p = 0; p < 2; p++) {
                int row = wn * 32 + p * 16 + (l & 7) + ((l >> 4) & 1) * 8;
                int col = ks * 16 + ((l >> 3) & 1) * 8;
                LDSM_X4(b[p * 2][0], b[p * 2][1], b[p * 2 + 1][0], b[p * 2 + 1][1],
                        sB[buf] + row * (SSTR * 2) + col * 2);
            }
#pragma unroll
            for (int mi = 0; mi < 4; mi++)
#pragma unroll
                for (int ni = 0; ni < 4; ni++)
                    MMA16816(d[mi][ni], a[mi], b[ni]);
        }
        __syncthreads();
    }

    // epilogue: scale by inv norms, write fp32 sim
#pragma unroll
    for (int mi = 0; mi < 4; mi++) {
        int r0 = bm + wm * 64 + mi * 16 + (l >> 2);
        int r1 = r0 + 8;
        float xi0 = g_xinv[r0], xi1 = g_xinv[r1];
#pragma unroll
        for (int ni = 0; ni < 4; ni++) {
            int c0 = bn + wn * 32 + ni * 8 + ((l & 3) << 1);
            float cv0 = g_cinv[c0], cv1 = g_cinv[c0 + 1];
            *(float2*)(g_sim + (size_t)r0 * NK + c0) =
                make_float2(d[mi][ni][0] * xi0 * cv0, d[mi][ni][1] * xi0 * cv1);
            *(float2*)(g_sim + (size_t)r1 * NK + c0) =
                make_float2(d[mi][ni][2] * xi1 * cv0, d[mi][ni][3] * xi1 * cv1);
        }
    }
}

// ---------------- per-row: gumbel noise, argmax, softmax, gather ----------------
__global__ __launch_bounds__(256) void rowops_kernel(
    const float* __restrict__ cb,
    float* __restrict__ zq, float* __restrict__ wout, float* __restrict__ idxout,
    uint32_t kh0, uint32_t kh1, uint32_t ks0, uint32_t ks1) {

    const int b = blockIdx.x;
    const int t = threadIdx.x;
    const int k0 = t << 2;
    const unsigned FULL = 0xffffffffu;
    const int lane = t & 31, warp = t >> 5;

    float4 s4 = *(const float4*)(g_sim + (size_t)b * NK + k0);
    float sim[4] = {s4.x, s4.y, s4.z, s4.w};
    float ts[4];
    float bv = -1.0f; int bk = 0;
#pragma unroll
    for (int j = 0; j < 4; j++) {
        uint32_t flat = (uint32_t)b * (uint32_t)NK + (uint32_t)(k0 + j);
        float uh = uniform_bits(rbits32(kh0, kh1, flat));
        float us = uniform_bits(rbits32(ks0, ks1, flat));
        float eh = -logf(uh);          // precise: feeds argmax
        float es = -__logf(us);        // fast: weights only
        float texp = expf(sim[j]);
        float h = texp / eh;
        ts[j] = __fdividef(texp, es);
        if (h > bv) { bv = h; bk = k0 + j; }
    }

    __shared__ float sred[8];
    __shared__ int   sredi[8];
    __shared__ int   s_idx;
    __shared__ float s_sum;

#pragma unroll
    for (int o = 16; o; o >>= 1) {
        float ov = __shfl_down_sync(FULL, bv, o);
        int   ok = __shfl_down_sync(FULL, bk, o);
        if (ov > bv || (ov == bv && ok < bk)) { bv = ov; bk = ok; }
    }
    if (lane == 0) { sred[warp] = bv; sredi[warp] = bk; }
    __syncthreads();
    if (t == 0) {
        float v = sred[0]; int k = sredi[0];
#pragma unroll
        for (int w = 1; w < 8; w++)
            if (sred[w] > v || (sred[w] == v && sredi[w] < k)) { v = sred[w]; k = sredi[w]; }
        s_idx = k;
    }

    float ls = (ts[0] + ts[1]) + (ts[2] + ts[3]);
#pragma unroll
    for (int o = 16; o; o >>= 1) ls += __shfl_xor_sync(FULL, ls, o);
    __syncthreads();
    if (lane == 0) sred[warp] = ls;
    __syncthreads();
    if (t == 0) {
        float ss = 0.0f;
#pragma unroll
        for (int w = 0; w < 8; w++) ss += sred[w];
        s_sum = ss;
    }
    __syncthreads();

    float inv = 1.0f / s_sum;
    float4 o4 = make_float4(ts[0] * inv, ts[1] * inv, ts[2] * inv, ts[3] * inv);
    *(float4*)(wout + (size_t)b * NK + k0) = o4;

    int idx = s_idx;
    const float2* crow = (const float2*)(cb + (size_t)idx * ND);
    ((float2*)(zq + (size_t)b * ND))[t] = crow[t];
    if (t == 0) idxout[b] = (float)idx;
}

// ---------------- host-side threefry ----------------
static void tf2x32_host(uint32_t k0, uint32_t k1, uint32_t x0, uint32_t x1,
                        uint32_t* o0, uint32_t* o1) {
    uint32_t k2 = k0 ^ k1 ^ 0x1BD11BDAu;
    x0 += k0; x1 += k1;
#define TF_ROT(r) { x0 += x1; x1 = (x1 << (r)) | (x1 >> (32 - (r))); x1 ^= x0; }
    TF_ROT(13) TF_ROT(15) TF_ROT(26) TF_ROT(6)
    x0 += k1; x1 += k2 + 1u;
    TF_ROT(17) TF_ROT(29) TF_ROT(16) TF_ROT(24)
    x0 += k2; x1 += k0 + 2u;
    TF_ROT(13) TF_ROT(15) TF_ROT(26) TF_ROT(6)
    x0 += k0; x1 += k1 + 3u;
    TF_ROT(17) TF_ROT(29) TF_ROT(16) TF_ROT(24)
    x0 += k1; x1 += k2 + 4u;
    TF_ROT(13) TF_ROT(15) TF_ROT(26) TF_ROT(6)
    x0 += k2; x1 += k0 + 5u;
#undef TF_ROT
    *o0 = x0; *o1 = x1;
}

extern "C" void kernel_launch(void* const* d_in, const int* in_sizes, int n_in,
                              void* d_out, int out_size) {
    const float* state = (const float*)d_in[0];   // (32768, 512)
    const float* cb    = (const float*)d_in[1];   // (1024, 512)

    float* out  = (float*)d_out;
    float* zq   = out;
    float* w    = out + (size_t)NB * ND;
    float* idxp = out + (size_t)NB * ND + (size_t)NB * NK;

    uint32_t kh0, kh1, ks0, ks1;
    tf2x32_host(0u, 42u, 0u, 0u, &kh0, &kh1);
    tf2x32_host(0u, 42u, 0u, 1u, &ks0, &ks1);

    const int n4a = NB * ND / 4, n4b = NK * ND / 4;
    split_kernel<<<(n4a + 255) / 256, 256>>>(state, 0, n4a);
    split_kernel<<<(n4b + 255) / 256, 256>>>(cb, 1, n4b);
    inv_norm_kernel<<<NB, 128>>>(state, 0);
    inv_norm_kernel<<<NK, 128>>>(cb, 1);

    dim3 ggrid(NK / BN, NB / BM);   // (8, 256); x fastest -> A panel L2 reuse
    gemm_mma_kernel<<<ggrid, 256>>>();

    rowops_kernel<<<NB, 256>>>(cb, zq, w, idxp, kh0, kh1, ks0, ks1);
}